// round 1
// baseline (speedup 1.0000x reference)
#include <cuda_runtime.h>
#include <math.h>

// Problem constants (fixed shapes from reference)
#define BB 16
#define SS 4096
#define DD 64
#define HH 8
#define NBK 64          // buckets per hash round
#define CHK 512         // chunks per batch (HH * NBK)
#define BSZ 64          // bucket/chunk size
#define KVN 128         // keys per chunk (current + look-back)

// -------------------- device scratch (no allocation allowed) --------------------
__device__ int   g_buckets[BB * HH * SS];                 // 2 MB
__device__ int   g_st[BB * HH * SS];                      // 2 MB  sorted original positions
__device__ float g_lse[BB * HH * SS];                     // 2 MB  per-round logits (unsorted layout)
__device__ float g_o[(size_t)BB * HH * SS * DD];          // 134 MB per-round outputs (unsorted layout)

// ==================== Kernel 1: LSH hashing ====================
// grid = BB * (SS/64) = 1024 CTAs, 256 threads.
// Computes buckets[b][h][t] = argmax over [d, -d] of d_i = sum_f qk[b,t,f] * rot[f,h,i]
// Shared: qT (64 tokens, f-major, stride 68) + rot (f-major, stride 260) aliased with dsH.
__global__ __launch_bounds__(256, 2) void hash_kernel(const float* __restrict__ qk,
                                                      const float* __restrict__ rot) {
    extern __shared__ float sm[];
    float* qT  = sm;              // 64*68 floats
    float* big = sm + 64 * 68;    // max(64*260, 256*68) = 17408 floats

    const int blk  = blockIdx.x;
    const int b    = blk >> 6;
    const int t0   = (blk & 63) * 64;
    const int tid  = threadIdx.x;
    const int w    = tid >> 5, l = tid & 31;

    // load rotations (64 f x 256 o), pad stride 260
    {
        const float4* rg = (const float4*)rot;
        for (int i4 = tid; i4 < 64 * 64; i4 += 256) {
            int f = i4 >> 6, o4 = i4 & 63;
            *(float4*)&big[f * 260 + o4 * 4] = rg[i4];
        }
    }
    // load q tile transposed: qT[f][i]
    for (int r = 0; r < 8; r++) {
        int i = w * 8 + r;
        float2 qv = ((const float2*)(qk + ((size_t)b * SS + t0 + i) * DD))[l];
        qT[(2 * l) * 68 + i]     = qv.x;
        qT[(2 * l + 1) * 68 + i] = qv.y;
    }
    __syncthreads();

    const int rt = tid >> 4, ct = tid & 15;
    float acc[4][16];
#pragma unroll
    for (int r = 0; r < 4; r++)
#pragma unroll
        for (int c = 0; c < 16; c++) acc[r][c] = 0.f;

    const float4* qT4 = (const float4*)qT;   // stride 17
    const float4* rt4 = (const float4*)big;  // stride 65
#pragma unroll 4
    for (int f = 0; f < 64; f++) {
        float4 q = qT4[f * 17 + rt];
        float qa[4] = {q.x, q.y, q.z, q.w};
#pragma unroll
        for (int g = 0; g < 4; g++) {
            float4 rv = rt4[f * 65 + g * 16 + ct];
            float ra[4] = {rv.x, rv.y, rv.z, rv.w};
#pragma unroll
            for (int r = 0; r < 4; r++)
#pragma unroll
                for (int c = 0; c < 4; c++)
                    acc[r][g * 4 + c] += qa[r] * ra[c];
        }
    }
    __syncthreads();   // rot dead, reuse region as dsH[o][t] stride 68

    float* dsH = big;
#pragma unroll
    for (int g = 0; g < 4; g++)
#pragma unroll
        for (int c = 0; c < 4; c++) {
            int o = g * 64 + ct * 4 + c;
            *(float4*)&dsH[o * 68 + rt * 4] =
                make_float4(acc[0][g * 4 + c], acc[1][g * 4 + c], acc[2][g * 4 + c], acc[3][g * 4 + c]);
        }
    __syncthreads();

    // argmax per (token, hash): 512 pairs, strict > keeps first occurrence
    for (int p = tid; p < 512; p += 256) {
        int t = p & 63, hh = p >> 6;
        const float* dv = &dsH[(hh * 32) * 68 + t];
        float best = dv[0];
        int bi = 0;
#pragma unroll
        for (int j = 1; j < 32; j++) { float vv = dv[j * 68];  if (vv > best) { best = vv; bi = j; } }
#pragma unroll
        for (int j = 0; j < 32; j++) { float vv = -dv[j * 68]; if (vv > best) { best = vv; bi = 32 + j; } }
        g_buckets[((size_t)(b * HH + hh)) * SS + t0 + t] = bi;
    }
}

// ==================== Kernel 2: stable counting sort per (b,h) ====================
// grid = 128 CTAs, 512 threads (16 warps x 256 tokens).
__global__ __launch_bounds__(512) void sort_kernel() {
    __shared__ int hist[16][64];
    __shared__ int run[16][64];
    __shared__ int totals[64];
    __shared__ int bstart[64];

    const int bh  = blockIdx.x;
    const int* bk = g_buckets + (size_t)bh * SS;
    int* dst      = g_st + (size_t)bh * SS;
    const int tid = threadIdx.x, w = tid >> 5, l = tid & 31;

    for (int i = tid; i < 1024; i += 512) ((int*)hist)[i] = 0;
    __syncthreads();

    // per-warp stable histogram
    for (int r = 0; r < 8; r++) {
        int t = w * 256 + r * 32 + l;
        int vv = bk[t];
        unsigned mask = __match_any_sync(0xffffffffu, vv);
        if (l == (int)(__ffs(mask) - 1)) hist[w][vv] += __popc(mask);
        __syncwarp();
    }
    __syncthreads();

    if (tid < 64) {
        int s = 0;
        for (int ww = 0; ww < 16; ww++) { int tmp = hist[ww][tid]; hist[ww][tid] = s; s += tmp; }
        totals[tid] = s;
    }
    __syncthreads();
    if (tid == 0) {
        int s = 0;
        for (int vv = 0; vv < 64; vv++) { bstart[vv] = s; s += totals[vv]; }
    }
    __syncthreads();
    for (int i = tid; i < 1024; i += 512) {
        int ww = i >> 6, vv = i & 63;
        run[ww][vv] = bstart[vv] + hist[ww][vv];
    }
    __syncthreads();

    // stable scatter
    for (int r = 0; r < 8; r++) {
        int t = w * 256 + r * 32 + l;
        int vv = bk[t];
        unsigned mask = __match_any_sync(0xffffffffu, vv);
        int rank = __popc(mask & ((1u << l) - 1u));
        int base = run[w][vv];
        __syncwarp();
        if (l == (int)(__ffs(mask) - 1)) run[w][vv] = base + __popc(mask);
        __syncwarp();
        dst[base + rank] = t;
    }
}

// ==================== Kernel 3: chunked attention ====================
// grid = BB*CHK = 8192 CTAs, 256 threads, ~87KB smem, 2 CTAs/SM.
__global__ __launch_bounds__(256, 2) void attn_kernel(const float* __restrict__ qk,
                                                      const float* __restrict__ v) {
    extern __shared__ char smc[];
    int*   tqi = (int*)smc;                       // 64
    int*   tki = (int*)(smc + 256);               // 128
    float* qT  = (float*)(smc + 768);             // 64 x 68   (f-major, q * D^-0.5)
    float* kT  = qT + 64 * 68;                    // 64 x 132  (f-major, normalized k); aliased as ds
    float* vs  = kT + 64 * 132;                   // 128 x 68  (row-major v)

    const int blk = blockIdx.x;
    const int b = blk >> 9, c = blk & 511;
    const int h  = c >> 6;
    const int cp = (c + 511) & 511;
    const int hp = cp >> 6;
    const int tid = threadIdx.x, w = tid >> 5, l = tid & 31;

    if (tid < 64) {
        int t = g_st[((size_t)(b * HH + h)) * SS + (c & 63) * 64 + tid];
        tqi[tid] = t;
        tki[tid] = t;
    } else if (tid < 128) {
        int i = tid - 64;
        tki[64 + i] = g_st[((size_t)(b * HH + hp)) * SS + (cp & 63) * 64 + i];
    }
    __syncthreads();

    // gather q rows (scaled), k rows (normalized), v rows
    for (int r = 0; r < 8; r++) {
        int i = w * 8 + r;
        float2 qv = ((const float2*)(qk + ((size_t)b * SS + tqi[i]) * DD))[l];
        qT[(2 * l) * 68 + i]     = qv.x * 0.125f;
        qT[(2 * l + 1) * 68 + i] = qv.y * 0.125f;
    }
    for (int r = 0; r < 16; r++) {
        int j = w * 16 + r;
        int t = tki[j];
        float2 kv = ((const float2*)(qk + ((size_t)b * SS + t) * DD))[l];
        float ssq = kv.x * kv.x + kv.y * kv.y;
#pragma unroll
        for (int o = 16; o; o >>= 1) ssq += __shfl_xor_sync(0xffffffffu, ssq, o);
        float inv = 1.0f / fmaxf(sqrtf(ssq), 1e-12f);
        kT[(2 * l) * 132 + j]     = kv.x * inv;
        kT[(2 * l + 1) * 132 + j] = kv.y * inv;
        float2 vv = ((const float2*)(v + ((size_t)b * SS + t) * DD))[l];
        vs[j * 68 + 2 * l]     = vv.x;
        vs[j * 68 + 2 * l + 1] = vv.y;
    }
    __syncthreads();

    // ---- QK^T: thread tile = rows 4*rt..+3, cols {4ct..+3} U {64+4ct..+3}
    const int rt = tid >> 4, ct = tid & 15;
    float acc[4][8];
#pragma unroll
    for (int r = 0; r < 4; r++)
#pragma unroll
        for (int cc = 0; cc < 8; cc++) acc[r][cc] = 0.f;

    const float4* qT4 = (const float4*)qT;  // stride 17
    const float4* kT4 = (const float4*)kT;  // stride 33
#pragma unroll 4
    for (int f = 0; f < 64; f++) {
        float4 q  = qT4[f * 17 + rt];
        float4 ka = kT4[f * 33 + ct];
        float4 kb = kT4[f * 33 + 16 + ct];
        float qa[4] = {q.x, q.y, q.z, q.w};
        float a0[4] = {ka.x, ka.y, ka.z, ka.w};
        float a1[4] = {kb.x, kb.y, kb.z, kb.w};
#pragma unroll
        for (int r = 0; r < 4; r++)
#pragma unroll
            for (int cc = 0; cc < 4; cc++) {
                acc[r][cc]     += qa[r] * a0[cc];
                acc[r][4 + cc] += qa[r] * a1[cc];
            }
    }
    __syncthreads();  // everyone done reading kT -> alias as ds

    // self-mask + store dots
    float* ds = kT;  // 64 x 132
    {
        int tq_r[4];
#pragma unroll
        for (int r = 0; r < 4; r++) tq_r[r] = tqi[rt * 4 + r];
#pragma unroll
        for (int r = 0; r < 4; r++) {
#pragma unroll
            for (int cc = 0; cc < 4; cc++) {
                if (tki[ct * 4 + cc]      == tq_r[r]) acc[r][cc]     = -5e4f;
                if (tki[64 + ct * 4 + cc] == tq_r[r]) acc[r][4 + cc] = -5e4f;
            }
            *(float4*)&ds[(rt * 4 + r) * 132 + ct * 4]      = make_float4(acc[r][0], acc[r][1], acc[r][2], acc[r][3]);
            *(float4*)&ds[(rt * 4 + r) * 132 + 64 + ct * 4] = make_float4(acc[r][4], acc[r][5], acc[r][6], acc[r][7]);
        }
    }
    __syncthreads();

    // ---- softmax: warp per row, 8 rows per warp
    for (int rr = 0; rr < 8; rr++) {
        int i = w * 8 + rr;
        float4 dv = *(float4*)&ds[i * 132 + 4 * l];
        float m = fmaxf(fmaxf(dv.x, dv.y), fmaxf(dv.z, dv.w));
#pragma unroll
        for (int o = 16; o; o >>= 1) m = fmaxf(m, __shfl_xor_sync(0xffffffffu, m, o));
        float e0 = __expf(dv.x - m), e1 = __expf(dv.y - m), e2 = __expf(dv.z - m), e3 = __expf(dv.w - m);
        float s = e0 + e1 + e2 + e3;
#pragma unroll
        for (int o = 16; o; o >>= 1) s += __shfl_xor_sync(0xffffffffu, s, o);
        float inv = 1.0f / s;
        *(float4*)&ds[i * 132 + 4 * l] = make_float4(e0 * inv, e1 * inv, e2 * inv, e3 * inv);
        if (l == 0) g_lse[((size_t)(b * HH + h)) * SS + tqi[i]] = m + __logf(s);
    }
    __syncthreads();

    // ---- P @ V: thread tile = rows 4*rt..+3, f-cols 4*ct..+3
    float o4[4][4];
#pragma unroll
    for (int r = 0; r < 4; r++)
#pragma unroll
        for (int cc = 0; cc < 4; cc++) o4[r][cc] = 0.f;
#pragma unroll 4
    for (int j = 0; j < 128; j++) {
        float4 vv = *(const float4*)&vs[j * 68 + 4 * ct];
        float va[4] = {vv.x, vv.y, vv.z, vv.w};
        float p0 = ds[(4 * rt + 0) * 132 + j];
        float p1 = ds[(4 * rt + 1) * 132 + j];
        float p2 = ds[(4 * rt + 2) * 132 + j];
        float p3 = ds[(4 * rt + 3) * 132 + j];
#pragma unroll
        for (int cc = 0; cc < 4; cc++) {
            o4[0][cc] += p0 * va[cc];
            o4[1][cc] += p1 * va[cc];
            o4[2][cc] += p2 * va[cc];
            o4[3][cc] += p3 * va[cc];
        }
    }
#pragma unroll
    for (int r = 0; r < 4; r++) {
        int t = tqi[4 * rt + r];
        *(float4*)&g_o[(((size_t)(b * HH + h)) * SS + t) * DD + 4 * ct] =
            make_float4(o4[r][0], o4[r][1], o4[r][2], o4[r][3]);
    }
}

// ==================== Kernel 4: combine hash rounds ====================
// warp per token; grid = BB*SS/8 CTAs of 256.
__global__ __launch_bounds__(256) void combine_kernel(float* __restrict__ out) {
    const int gw = (blockIdx.x * 256 + threadIdx.x) >> 5;
    const int l  = threadIdx.x & 31;
    const int b  = gw >> 12, t = gw & (SS - 1);

    float lg[HH];
#pragma unroll
    for (int hh = 0; hh < HH; hh++) lg[hh] = g_lse[((size_t)(b * HH + hh)) * SS + t];
    float m = lg[0];
#pragma unroll
    for (int hh = 1; hh < HH; hh++) m = fmaxf(m, lg[hh]);
    float wv[HH];
    float wsum = 0.f;
#pragma unroll
    for (int hh = 0; hh < HH; hh++) { wv[hh] = __expf(lg[hh] - m); wsum += wv[hh]; }
    float inv = 1.0f / wsum;

    float2 accv = make_float2(0.f, 0.f);
#pragma unroll
    for (int hh = 0; hh < HH; hh++) {
        float2 ov = ((const float2*)(g_o + (((size_t)(b * HH + hh)) * SS + t) * DD))[l];
        float wgt = wv[hh] * inv;
        accv.x += wgt * ov.x;
        accv.y += wgt * ov.y;
    }
    ((float2*)(out + ((size_t)b * SS + t) * DD))[l] = accv;
}

// ==================== launch ====================
extern "C" void kernel_launch(void* const* d_in, const int* in_sizes, int n_in,
                              void* d_out, int out_size) {
    const float* qk  = (const float*)d_in[0];
    const float* v   = (const float*)d_in[1];
    const float* rot = (const float*)d_in[2];
    float* out = (float*)d_out;

    (void)in_sizes; (void)n_in; (void)out_size;

    const int hash_smem = 87040;   // 64*68*4 + 256*68*4
    const int attn_smem = 86784;   // 768 + 64*68*4 + 64*132*4 + 128*68*4
    cudaFuncSetAttribute(hash_kernel, cudaFuncAttributeMaxDynamicSharedMemorySize, hash_smem);
    cudaFuncSetAttribute(attn_kernel, cudaFuncAttributeMaxDynamicSharedMemorySize, attn_smem);

    hash_kernel<<<BB * (SS / 64), 256, hash_smem>>>(qk, rot);
    sort_kernel<<<BB * HH, 512>>>();
    attn_kernel<<<BB * CHK, 256, attn_smem>>>(qk, v);
    combine_kernel<<<(BB * SS) / 8, 256>>>(out);
}

// round 3
// speedup vs baseline: 1.2196x; 1.2196x over previous
#include <cuda_runtime.h>
#include <math.h>

// Problem constants (fixed shapes from reference)
#define BB 16
#define SS 4096
#define DD 64
#define HH 8
#define NBK 64          // buckets per hash round
#define CHK 512         // chunks per batch (HH * NBK)
#define BSZ 64          // bucket/chunk size
#define KVN 128         // keys per chunk (current + look-back)

// -------------------- device scratch (no allocation allowed) --------------------
__device__ int   g_buckets[BB * HH * SS];                 // 2 MB
__device__ int   g_st[BB * HH * SS];                      // 2 MB  sorted original positions
__device__ float g_lse[BB * HH * SS];                     // 2 MB  per-round logits (unsorted layout)
__device__ float g_o[(size_t)BB * HH * SS * DD];          // 134 MB per-round outputs (unsorted layout)

// -------------------- helpers --------------------
__device__ __forceinline__ float to_tf32(float x) {
    unsigned u;
    asm("cvt.rna.tf32.f32 %0, %1;" : "=r"(u) : "f"(x));
    return __uint_as_float(u);
}

__device__ __forceinline__ void mma_tf32(float& c0, float& c1, float& c2, float& c3,
                                         unsigned a0, unsigned a1, unsigned a2, unsigned a3,
                                         unsigned b0, unsigned b1) {
    asm volatile("mma.sync.aligned.m16n8k8.row.col.f32.tf32.tf32.f32 "
                 "{%0,%1,%2,%3},{%4,%5,%6,%7},{%8,%9},{%0,%1,%2,%3};"
                 : "+f"(c0), "+f"(c1), "+f"(c2), "+f"(c3)
                 : "r"(a0), "r"(a1), "r"(a2), "r"(a3), "r"(b0), "r"(b1));
}

// ==================== Kernel 1: LSH hashing (fp32 — argmax is discrete) ====================
// grid = BB * (SS/64) = 1024 CTAs, 256 threads.
__global__ __launch_bounds__(256, 2) void hash_kernel(const float* __restrict__ qk,
                                                      const float* __restrict__ rot) {
    extern __shared__ float sm[];
    float* qT  = sm;              // 64*68 floats
    float* big = sm + 64 * 68;    // max(64*260, 256*68) = 17408 floats

    const int blk  = blockIdx.x;
    const int b    = blk >> 6;
    const int t0   = (blk & 63) * 64;
    const int tid  = threadIdx.x;
    const int w    = tid >> 5, l = tid & 31;

    // load rotations (64 f x 256 o), pad stride 260
    {
        const float4* rg = (const float4*)rot;
        for (int i4 = tid; i4 < 64 * 64; i4 += 256) {
            int f = i4 >> 6, o4 = i4 & 63;
            *(float4*)&big[f * 260 + o4 * 4] = rg[i4];
        }
    }
    // load q tile transposed: qT[f][i]
    for (int r = 0; r < 8; r++) {
        int i = w * 8 + r;
        float2 qv = ((const float2*)(qk + ((size_t)b * SS + t0 + i) * DD))[l];
        qT[(2 * l) * 68 + i]     = qv.x;
        qT[(2 * l + 1) * 68 + i] = qv.y;
    }
    __syncthreads();

    const int rt = tid >> 4, ct = tid & 15;
    float acc[4][16];
#pragma unroll
    for (int r = 0; r < 4; r++)
#pragma unroll
        for (int c = 0; c < 16; c++) acc[r][c] = 0.f;

    const float4* qT4 = (const float4*)qT;   // stride 17
    const float4* rt4 = (const float4*)big;  // stride 65
#pragma unroll 4
    for (int f = 0; f < 64; f++) {
        float4 q = qT4[f * 17 + rt];
        float qa[4] = {q.x, q.y, q.z, q.w};
#pragma unroll
        for (int g = 0; g < 4; g++) {
            float4 rv = rt4[f * 65 + g * 16 + ct];
            float ra[4] = {rv.x, rv.y, rv.z, rv.w};
#pragma unroll
            for (int r = 0; r < 4; r++)
#pragma unroll
                for (int c = 0; c < 4; c++)
                    acc[r][g * 4 + c] += qa[r] * ra[c];
        }
    }
    __syncthreads();   // rot dead, reuse region as dsH[o][t] stride 68

    float* dsH = big;
#pragma unroll
    for (int g = 0; g < 4; g++)
#pragma unroll
        for (int c = 0; c < 4; c++) {
            int o = g * 64 + ct * 4 + c;
            *(float4*)&dsH[o * 68 + rt * 4] =
                make_float4(acc[0][g * 4 + c], acc[1][g * 4 + c], acc[2][g * 4 + c], acc[3][g * 4 + c]);
        }
    __syncthreads();

    // argmax per (token, hash): 512 pairs, strict > keeps first occurrence
    for (int p = tid; p < 512; p += 256) {
        int t = p & 63, hh = p >> 6;
        const float* dv = &dsH[(hh * 32) * 68 + t];
        float best = dv[0];
        int bi = 0;
#pragma unroll
        for (int j = 1; j < 32; j++) { float vv = dv[j * 68];  if (vv > best) { best = vv; bi = j; } }
#pragma unroll
        for (int j = 0; j < 32; j++) { float vv = -dv[j * 68]; if (vv > best) { best = vv; bi = 32 + j; } }
        g_buckets[((size_t)(b * HH + hh)) * SS + t0 + t] = bi;
    }
}

// ==================== Kernel 2: stable counting sort per (b,h) ====================
__global__ __launch_bounds__(512) void sort_kernel() {
    __shared__ int hist[16][64];
    __shared__ int run[16][64];
    __shared__ int totals[64];
    __shared__ int bstart[64];

    const int bh  = blockIdx.x;
    const int* bk = g_buckets + (size_t)bh * SS;
    int* dst      = g_st + (size_t)bh * SS;
    const int tid = threadIdx.x, w = tid >> 5, l = tid & 31;

    for (int i = tid; i < 1024; i += 512) ((int*)hist)[i] = 0;
    __syncthreads();

    for (int r = 0; r < 8; r++) {
        int t = w * 256 + r * 32 + l;
        int vv = bk[t];
        unsigned mask = __match_any_sync(0xffffffffu, vv);
        if (l == (int)(__ffs(mask) - 1)) hist[w][vv] += __popc(mask);
        __syncwarp();
    }
    __syncthreads();

    if (tid < 64) {
        int s = 0;
        for (int ww = 0; ww < 16; ww++) { int tmp = hist[ww][tid]; hist[ww][tid] = s; s += tmp; }
        totals[tid] = s;
    }
    __syncthreads();
    if (tid == 0) {
        int s = 0;
        for (int vv = 0; vv < 64; vv++) { bstart[vv] = s; s += totals[vv]; }
    }
    __syncthreads();
    for (int i = tid; i < 1024; i += 512) {
        int ww = i >> 6, vv = i & 63;
        run[ww][vv] = bstart[vv] + hist[ww][vv];
    }
    __syncthreads();

    for (int r = 0; r < 8; r++) {
        int t = w * 256 + r * 32 + l;
        int vv = bk[t];
        unsigned mask = __match_any_sync(0xffffffffu, vv);
        int rank = __popc(mask & ((1u << l) - 1u));
        int base = run[w][vv];
        __syncwarp();
        if (l == (int)(__ffs(mask) - 1)) run[w][vv] = base + __popc(mask);
        __syncwarp();
        dst[base + rank] = t;
    }
}

// ==================== Kernel 3: chunked attention (tf32 tensor cores) ====================
// grid = BB*CHK = 8192 CTAs, 256 threads (8 warps), 86784B smem, 2 CTAs/SM.
// Smem layout:
//   tqi[64], tki[128]               (768 B incl pad)
//   Qsm[64][68]  row-major tf32 (q * D^-0.5)
//   Ksm[128][68] row-major tf32 (L2-normalized k)   -- aliased as ds[64][132] after QK
//   VT [64][132] f-major  tf32 (VT[f][j] = v[j][f])
__global__ __launch_bounds__(256, 2) void attn_kernel(const float* __restrict__ qk,
                                                      const float* __restrict__ v) {
    extern __shared__ char smc[];
    int*   tqi = (int*)smc;                       // 64 ints
    int*   tki = (int*)(smc + 256);               // 128 ints
    float* Qsm = (float*)(smc + 768);             // 64*68
    float* Ksm = Qsm + 64 * 68;                   // 128*68  (aliased as ds 64*132)
    float* VT  = Ksm + 128 * 68;                  // 64*132

    const int blk = blockIdx.x;
    const int b = blk >> 9, c = blk & 511;
    const int h  = c >> 6;
    const int cp = (c + 511) & 511;
    const int hp = cp >> 6;
    const int tid = threadIdx.x, w = tid >> 5, l = tid & 31;
    const int gID = l >> 2, tig = l & 3;
    const int wm = w & 3, wn = w >> 2;

    if (tid < 64) {
        int t = g_st[((size_t)(b * HH + h)) * SS + (c & 63) * 64 + tid];
        tqi[tid] = t;
        tki[tid] = t;
    } else if (tid < 128) {
        int i = tid - 64;
        tki[64 + i] = g_st[((size_t)(b * HH + hp)) * SS + (cp & 63) * 64 + i];
    }
    __syncthreads();

    // ---- gather: q (scaled), k (normalized), v -> tf32 smem
    for (int r = 0; r < 8; r++) {
        int i = w * 8 + r;
        float2 qv = ((const float2*)(qk + ((size_t)b * SS + tqi[i]) * DD))[l];
        *(float2*)&Qsm[i * 68 + 2 * l] = make_float2(to_tf32(qv.x * 0.125f), to_tf32(qv.y * 0.125f));
    }
    for (int r = 0; r < 16; r++) {
        int j = w * 16 + r;
        int t = tki[j];
        float2 kv = ((const float2*)(qk + ((size_t)b * SS + t) * DD))[l];
        float ssq = kv.x * kv.x + kv.y * kv.y;
#pragma unroll
        for (int o = 16; o; o >>= 1) ssq += __shfl_xor_sync(0xffffffffu, ssq, o);
        float inv = 1.0f / fmaxf(sqrtf(ssq), 1e-12f);
        *(float2*)&Ksm[j * 68 + 2 * l] = make_float2(to_tf32(kv.x * inv), to_tf32(kv.y * inv));
        float2 vv = ((const float2*)(v + ((size_t)b * SS + t) * DD))[l];
        VT[(2 * l) * 132 + j]     = to_tf32(vv.x);
        VT[(2 * l + 1) * 132 + j] = to_tf32(vv.y);
    }
    __syncthreads();

    // ---- QK^T via tf32 mma: warp tile = rows [wm*16, +16), cols [wn*64, +64)
    // k-permutation: thread tig owns k-cols {2tig, 2tig+1} in both A and B (sum-invariant).
    float cqk[8][4];
#pragma unroll
    for (int nt = 0; nt < 8; nt++)
#pragma unroll
        for (int r = 0; r < 4; r++) cqk[nt][r] = 0.f;

#pragma unroll
    for (int k = 0; k < 8; k++) {
        float2 aA = *(float2*)&Qsm[(wm * 16 + gID) * 68 + k * 8 + 2 * tig];
        float2 aB = *(float2*)&Qsm[(wm * 16 + gID + 8) * 68 + k * 8 + 2 * tig];
        unsigned a0 = __float_as_uint(aA.x), a2 = __float_as_uint(aA.y);
        unsigned a1 = __float_as_uint(aB.x), a3 = __float_as_uint(aB.y);
#pragma unroll
        for (int nt = 0; nt < 8; nt++) {
            float2 bb = *(float2*)&Ksm[(wn * 64 + nt * 8 + gID) * 68 + k * 8 + 2 * tig];
            mma_tf32(cqk[nt][0], cqk[nt][1], cqk[nt][2], cqk[nt][3],
                     a0, a1, a2, a3, __float_as_uint(bb.x), __float_as_uint(bb.y));
        }
    }
    __syncthreads();   // all warps done reading Ksm -> alias as ds

    float* ds = Ksm;   // 64 x 132
#pragma unroll
    for (int nt = 0; nt < 8; nt++) {
        int col = wn * 64 + nt * 8 + 2 * tig;
        int row = wm * 16 + gID;
        *(float2*)&ds[row * 132 + col]       = make_float2(cqk[nt][0], cqk[nt][1]);
        *(float2*)&ds[(row + 8) * 132 + col] = make_float2(cqk[nt][2], cqk[nt][3]);
    }
    __syncthreads();

    // ---- softmax: warp per row (8 rows/warp); self-mask applied here
    for (int rr = 0; rr < 8; rr++) {
        int i = w * 8 + rr;
        float4 dv = *(float4*)&ds[i * 132 + 4 * l];
        int4 tk4 = *(int4*)&tki[4 * l];
        int tq = tqi[i];
        if (tk4.x == tq) dv.x = -5e4f;
        if (tk4.y == tq) dv.y = -5e4f;
        if (tk4.z == tq) dv.z = -5e4f;
        if (tk4.w == tq) dv.w = -5e4f;
        float m = fmaxf(fmaxf(dv.x, dv.y), fmaxf(dv.z, dv.w));
#pragma unroll
        for (int o = 16; o; o >>= 1) m = fmaxf(m, __shfl_xor_sync(0xffffffffu, m, o));
        float e0 = __expf(dv.x - m), e1 = __expf(dv.y - m), e2 = __expf(dv.z - m), e3 = __expf(dv.w - m);
        float s = e0 + e1 + e2 + e3;
#pragma unroll
        for (int o = 16; o; o >>= 1) s += __shfl_xor_sync(0xffffffffu, s, o);
        float inv = 1.0f / s;
        *(float4*)&ds[i * 132 + 4 * l] =
            make_float4(to_tf32(e0 * inv), to_tf32(e1 * inv), to_tf32(e2 * inv), to_tf32(e3 * inv));
        if (l == 0) g_lse[((size_t)(b * HH + h)) * SS + tqi[i]] = m + __logf(s);
    }
    __syncthreads();

    // ---- P @ V via tf32 mma: warp tile = rows [wm*16,+16), f-cols [wn*32,+32), K=128
    float oacc[4][4];
#pragma unroll
    for (int nt = 0; nt < 4; nt++)
#pragma unroll
        for (int r = 0; r < 4; r++) oacc[nt][r] = 0.f;

#pragma unroll 4
    for (int k = 0; k < 16; k++) {
        float2 aA = *(float2*)&ds[(wm * 16 + gID) * 132 + k * 8 + 2 * tig];
        float2 aB = *(float2*)&ds[(wm * 16 + gID + 8) * 132 + k * 8 + 2 * tig];
        unsigned a0 = __float_as_uint(aA.x), a2 = __float_as_uint(aA.y);
        unsigned a1 = __float_as_uint(aB.x), a3 = __float_as_uint(aB.y);
#pragma unroll
        for (int nt = 0; nt < 4; nt++) {
            float2 bb = *(float2*)&VT[(wn * 32 + nt * 8 + gID) * 132 + k * 8 + 2 * tig];
            mma_tf32(oacc[nt][0], oacc[nt][1], oacc[nt][2], oacc[nt][3],
                     a0, a1, a2, a3, __float_as_uint(bb.x), __float_as_uint(bb.y));
        }
    }

    // ---- scatter outputs by original token position
    {
        int row = wm * 16 + gID;
        int t0r = tqi[row], t1r = tqi[row + 8];
        float* o0 = g_o + (((size_t)(b * HH + h)) * SS + t0r) * DD;
        float* o1 = g_o + (((size_t)(b * HH + h)) * SS + t1r) * DD;
#pragma unroll
        for (int nt = 0; nt < 4; nt++) {
            int col = wn * 32 + nt * 8 + 2 * tig;
            *(float2*)&o0[col] = make_float2(oacc[nt][0], oacc[nt][1]);
            *(float2*)&o1[col] = make_float2(oacc[nt][2], oacc[nt][3]);
        }
    }
}

// ==================== Kernel 4: combine hash rounds ====================
__global__ __launch_bounds__(256) void combine_kernel(float* __restrict__ out) {
    const int gw = (blockIdx.x * 256 + threadIdx.x) >> 5;
    const int l  = threadIdx.x & 31;
    const int b  = gw >> 12, t = gw & (SS - 1);

    float lg[HH];
#pragma unroll
    for (int hh = 0; hh < HH; hh++) lg[hh] = g_lse[((size_t)(b * HH + hh)) * SS + t];
    float m = lg[0];
#pragma unroll
    for (int hh = 1; hh < HH; hh++) m = fmaxf(m, lg[hh]);
    float wv[HH];
    float wsum = 0.f;
#pragma unroll
    for (int hh = 0; hh < HH; hh++) { wv[hh] = __expf(lg[hh] - m); wsum += wv[hh]; }
    float inv = 1.0f / wsum;

    float2 accv = make_float2(0.f, 0.f);
#pragma unroll
    for (int hh = 0; hh < HH; hh++) {
        float2 ov = ((const float2*)(g_o + (((size_t)(b * HH + hh)) * SS + t) * DD))[l];
        float wgt = wv[hh] * inv;
        accv.x += wgt * ov.x;
        accv.y += wgt * ov.y;
    }
    ((float2*)(out + ((size_t)b * SS + t) * DD))[l] = accv;
}

// ==================== launch ====================
extern "C" void kernel_launch(void* const* d_in, const int* in_sizes, int n_in,
                              void* d_out, int out_size) {
    const float* qk  = (const float*)d_in[0];
    const float* v   = (const float*)d_in[1];
    const float* rot = (const float*)d_in[2];
    float* out = (float*)d_out;

    (void)in_sizes; (void)n_in; (void)out_size;

    const int hash_smem = 87040;   // 64*68*4 + 256*68*4
    const int attn_smem = 86784;   // 768 + 64*68*4 + 128*68*4 + 64*132*4
    cudaFuncSetAttribute(hash_kernel, cudaFuncAttributeMaxDynamicSharedMemorySize, hash_smem);
    cudaFuncSetAttribute(attn_kernel, cudaFuncAttributeMaxDynamicSharedMemorySize, attn_smem);

    hash_kernel<<<BB * (SS / 64), 256, hash_smem>>>(qk, rot);
    sort_kernel<<<BB * HH, 512>>>();
    attn_kernel<<<BB * CHK, 256, attn_smem>>>(qk, v);
    combine_kernel<<<(BB * SS) / 8, 256>>>(out);
}

// round 5
// speedup vs baseline: 1.9714x; 1.6164x over previous
#include <cuda_runtime.h>
#include <cuda_fp16.h>
#include <math.h>

// Problem constants (fixed shapes from reference)
#define BB 16
#define SS 4096
#define DD 64
#define HH 8
#define NBK 64          // buckets per hash round
#define CHK 512         // chunks per batch (HH * NBK)
#define BSZ 64          // bucket/chunk size
#define KVN 128         // keys per chunk (current + look-back)

// -------------------- device scratch (no allocation allowed) --------------------
__device__ int   g_buckets[BB * HH * SS];                 // 2 MB
__device__ int   g_st[BB * HH * SS];                      // 2 MB  sorted original positions
__device__ float g_lse[BB * HH * SS];                     // 2 MB  per-round logits (unsorted layout)
__device__ float g_o[(size_t)BB * HH * SS * DD];          // 134 MB per-round outputs (unsorted layout)

// -------------------- helpers --------------------
__device__ __forceinline__ unsigned h2_u32(__half2 h) {
    union { __half2 h; unsigned u; } cvt;
    cvt.h = h;
    return cvt.u;
}

__device__ __forceinline__ void mma_f16(float* c,
                                        unsigned a0, unsigned a1, unsigned a2, unsigned a3,
                                        unsigned b0, unsigned b1) {
    asm volatile("mma.sync.aligned.m16n8k16.row.col.f32.f16.f16.f32 "
                 "{%0,%1,%2,%3},{%4,%5,%6,%7},{%8,%9},{%0,%1,%2,%3};"
                 : "+f"(c[0]), "+f"(c[1]), "+f"(c[2]), "+f"(c[3])
                 : "r"(a0), "r"(a1), "r"(a2), "r"(a3), "r"(b0), "r"(b1));
}

// ==================== Kernel 1: LSH hashing (fp32 — argmax is discrete) ====================
// grid = BB * (SS/64) = 1024 CTAs, 256 threads.
__global__ __launch_bounds__(256, 2) void hash_kernel(const float* __restrict__ qk,
                                                      const float* __restrict__ rot) {
    extern __shared__ float sm[];
    float* qT  = sm;              // 64*68 floats
    float* big = sm + 64 * 68;    // max(64*260, 256*68) = 17408 floats

    const int blk  = blockIdx.x;
    const int b    = blk >> 6;
    const int t0   = (blk & 63) * 64;
    const int tid  = threadIdx.x;
    const int w    = tid >> 5, l = tid & 31;

    {
        const float4* rg = (const float4*)rot;
        for (int i4 = tid; i4 < 64 * 64; i4 += 256) {
            int f = i4 >> 6, o4 = i4 & 63;
            *(float4*)&big[f * 260 + o4 * 4] = rg[i4];
        }
    }
    for (int r = 0; r < 8; r++) {
        int i = w * 8 + r;
        float2 qv = ((const float2*)(qk + ((size_t)b * SS + t0 + i) * DD))[l];
        qT[(2 * l) * 68 + i]     = qv.x;
        qT[(2 * l + 1) * 68 + i] = qv.y;
    }
    __syncthreads();

    const int rt = tid >> 4, ct = tid & 15;
    float acc[4][16];
#pragma unroll
    for (int r = 0; r < 4; r++)
#pragma unroll
        for (int c = 0; c < 16; c++) acc[r][c] = 0.f;

    const float4* qT4 = (const float4*)qT;   // stride 17
    const float4* rt4 = (const float4*)big;  // stride 65
#pragma unroll 4
    for (int f = 0; f < 64; f++) {
        float4 q = qT4[f * 17 + rt];
        float qa[4] = {q.x, q.y, q.z, q.w};
#pragma unroll
        for (int g = 0; g < 4; g++) {
            float4 rv = rt4[f * 65 + g * 16 + ct];
            float ra[4] = {rv.x, rv.y, rv.z, rv.w};
#pragma unroll
            for (int r = 0; r < 4; r++)
#pragma unroll
                for (int c = 0; c < 4; c++)
                    acc[r][g * 4 + c] += qa[r] * ra[c];
        }
    }
    __syncthreads();

    float* dsH = big;
#pragma unroll
    for (int g = 0; g < 4; g++)
#pragma unroll
        for (int c = 0; c < 4; c++) {
            int o = g * 64 + ct * 4 + c;
            *(float4*)&dsH[o * 68 + rt * 4] =
                make_float4(acc[0][g * 4 + c], acc[1][g * 4 + c], acc[2][g * 4 + c], acc[3][g * 4 + c]);
        }
    __syncthreads();

    for (int p = tid; p < 512; p += 256) {
        int t = p & 63, hh = p >> 6;
        const float* dv = &dsH[(hh * 32) * 68 + t];
        float best = dv[0];
        int bi = 0;
#pragma unroll
        for (int j = 1; j < 32; j++) { float vv = dv[j * 68];  if (vv > best) { best = vv; bi = j; } }
#pragma unroll
        for (int j = 0; j < 32; j++) { float vv = -dv[j * 68]; if (vv > best) { best = vv; bi = 32 + j; } }
        g_buckets[((size_t)(b * HH + hh)) * SS + t0 + t] = bi;
    }
}

// ==================== Kernel 2: stable counting sort per (b,h) ====================
__global__ __launch_bounds__(512) void sort_kernel() {
    __shared__ int hist[16][64];
    __shared__ int run[16][64];
    __shared__ int totals[64];
    __shared__ int bstart[64];

    const int bh  = blockIdx.x;
    const int* bk = g_buckets + (size_t)bh * SS;
    int* dst      = g_st + (size_t)bh * SS;
    const int tid = threadIdx.x, w = tid >> 5, l = tid & 31;

    for (int i = tid; i < 1024; i += 512) ((int*)hist)[i] = 0;
    __syncthreads();

    for (int r = 0; r < 8; r++) {
        int t = w * 256 + r * 32 + l;
        int vv = bk[t];
        unsigned mask = __match_any_sync(0xffffffffu, vv);
        if (l == (int)(__ffs(mask) - 1)) hist[w][vv] += __popc(mask);
        __syncwarp();
    }
    __syncthreads();

    if (tid < 64) {
        int s = 0;
        for (int ww = 0; ww < 16; ww++) { int tmp = hist[ww][tid]; hist[ww][tid] = s; s += tmp; }
        totals[tid] = s;
    }
    __syncthreads();
    if (tid == 0) {
        int s = 0;
        for (int vv = 0; vv < 64; vv++) { bstart[vv] = s; s += totals[vv]; }
    }
    __syncthreads();
    for (int i = tid; i < 1024; i += 512) {
        int ww = i >> 6, vv = i & 63;
        run[ww][vv] = bstart[vv] + hist[ww][vv];
    }
    __syncthreads();

    for (int r = 0; r < 8; r++) {
        int t = w * 256 + r * 32 + l;
        int vv = bk[t];
        unsigned mask = __match_any_sync(0xffffffffu, vv);
        int rank = __popc(mask & ((1u << l) - 1u));
        int base = run[w][vv];
        __syncwarp();
        if (l == (int)(__ffs(mask) - 1)) run[w][vv] = base + __popc(mask);
        __syncwarp();
        dst[base + rank] = t;
    }
}

// ==================== Kernel 3: chunked attention (fp16 mma, register softmax) ====================
// grid = BB*CHK = 8192 CTAs, 256 threads (8 warps), 49920B smem.
// Warp (wm, wn): QK tile rows [wm*16,+16), cols [wn*64,+64). Register softmax with
// cross-wn (m,s) merge; PV over this warp's 64-key half, partials summed via Dx smem.
// Smem:
//   tqi[64]@0, tki[128]@256, stats[2][64][2]f@768
//   Qsm half[64][80]@1792, Ksm half[128][80]@12032, VT half[64][136]@32512
//   Dx float[64][66] aliases @1792 (Qsm/Ksm dead after QK)
__global__ __launch_bounds__(256, 3) void attn_kernel(const float* __restrict__ qk,
                                                      const float* __restrict__ v) {
    extern __shared__ char smc[];
    int*    tqi   = (int*)smc;
    int*    tki   = (int*)(smc + 256);
    float*  stats = (float*)(smc + 768);        // [wn*64 + row]*2 -> {m, s}
    __half* Qsm   = (__half*)(smc + 1792);      // stride 80
    __half* Ksm   = (__half*)(smc + 12032);     // stride 80
    __half* VT    = (__half*)(smc + 32512);     // stride 136, VT[f][j] = v[j][f]
    float*  Dx    = (float*)(smc + 1792);       // 64 x 66

    const int blk = blockIdx.x;
    const int b = blk >> 9, c = blk & 511;
    const int h  = c >> 6;
    const int cp = (c + 511) & 511;
    const int hp = cp >> 6;
    const int tid = threadIdx.x, w = tid >> 5, l = tid & 31;
    const int gID = l >> 2, tig = l & 3;
    const int wm = w & 3, wn = w >> 2;
    const int arow = wm * 16 + gID;

    if (tid < 64) {
        int t = g_st[((size_t)(b * HH + h)) * SS + (c & 63) * 64 + tid];
        tqi[tid] = t;
        tki[tid] = t;
    } else if (tid < 128) {
        int i = tid - 64;
        tki[64 + i] = g_st[((size_t)(b * HH + hp)) * SS + (cp & 63) * 64 + i];
    }
    __syncthreads();

    // ---- gather: q (scaled), k (normalized), v -> fp16 smem
    for (int r = 0; r < 8; r++) {
        int i = w * 8 + r;
        float2 qv = ((const float2*)(qk + ((size_t)b * SS + tqi[i]) * DD))[l];
        *(__half2*)&Qsm[i * 80 + 2 * l] = __floats2half2_rn(qv.x * 0.125f, qv.y * 0.125f);
    }
    for (int r = 0; r < 16; r++) {
        int j = w * 16 + r;
        int t = tki[j];
        float2 kv = ((const float2*)(qk + ((size_t)b * SS + t) * DD))[l];
        float ssq = kv.x * kv.x + kv.y * kv.y;
#pragma unroll
        for (int o = 16; o; o >>= 1) ssq += __shfl_xor_sync(0xffffffffu, ssq, o);
        float inv = 1.0f / fmaxf(sqrtf(ssq), 1e-12f);
        *(__half2*)&Ksm[j * 80 + 2 * l] = __floats2half2_rn(kv.x * inv, kv.y * inv);
        float2 vv = ((const float2*)(v + ((size_t)b * SS + t) * DD))[l];
        VT[(2 * l) * 136 + j]     = __float2half_rn(vv.x);
        VT[(2 * l + 1) * 136 + j] = __float2half_rn(vv.y);
    }
    __syncthreads();

    // ---- QK^T via fp16 mma (K=64, 4 k16 steps, 8 n-tiles)
    // k-permutation per (s,tig): kL={16s+4tig,+1}, kH={16s+4tig+2,+3}; one LDS.64 per row/col.
    float cqk[8][4];
#pragma unroll
    for (int nt = 0; nt < 8; nt++)
#pragma unroll
        for (int r = 0; r < 4; r++) cqk[nt][r] = 0.f;

#pragma unroll
    for (int s = 0; s < 4; s++) {
        uint2 A0 = *(uint2*)&Qsm[arow * 80 + s * 16 + 4 * tig];        // a0 (kL), a2 (kH)
        uint2 A1 = *(uint2*)&Qsm[(arow + 8) * 80 + s * 16 + 4 * tig];  // a1, a3
#pragma unroll
        for (int nt = 0; nt < 8; nt++) {
            uint2 Bv = *(uint2*)&Ksm[(wn * 64 + nt * 8 + gID) * 80 + s * 16 + 4 * tig]; // b0, b1
            mma_f16(cqk[nt], A0.x, A1.x, A0.y, A1.y, Bv.x, Bv.y);
        }
    }

    // ---- self-mask (thread cols: wn*64 + nt*8 + 2tig + {0,1})
    const int tq0 = tqi[arow], tq1 = tqi[arow + 8];
#pragma unroll
    for (int nt = 0; nt < 8; nt++) {
        int2 kk = *(int2*)&tki[wn * 64 + nt * 8 + 2 * tig];
        if (kk.x == tq0) cqk[nt][0] = -5e4f;
        if (kk.y == tq0) cqk[nt][1] = -5e4f;
        if (kk.x == tq1) cqk[nt][2] = -5e4f;
        if (kk.y == tq1) cqk[nt][3] = -5e4f;
    }

    // ---- register softmax: per-row partial (m, s) within warp half, merge across wn
    float m0 = -3.4e38f, m1 = -3.4e38f;
#pragma unroll
    for (int nt = 0; nt < 8; nt++) {
        m0 = fmaxf(m0, fmaxf(cqk[nt][0], cqk[nt][1]));
        m1 = fmaxf(m1, fmaxf(cqk[nt][2], cqk[nt][3]));
    }
    m0 = fmaxf(m0, __shfl_xor_sync(0xffffffffu, m0, 1));
    m0 = fmaxf(m0, __shfl_xor_sync(0xffffffffu, m0, 2));
    m1 = fmaxf(m1, __shfl_xor_sync(0xffffffffu, m1, 1));
    m1 = fmaxf(m1, __shfl_xor_sync(0xffffffffu, m1, 2));
    float s0 = 0.f, s1 = 0.f;
#pragma unroll
    for (int nt = 0; nt < 8; nt++) {
        float e0 = __expf(cqk[nt][0] - m0), e1 = __expf(cqk[nt][1] - m0);
        float e2 = __expf(cqk[nt][2] - m1), e3 = __expf(cqk[nt][3] - m1);
        cqk[nt][0] = e0; cqk[nt][1] = e1; cqk[nt][2] = e2; cqk[nt][3] = e3;
        s0 += e0 + e1; s1 += e2 + e3;
    }
    s0 += __shfl_xor_sync(0xffffffffu, s0, 1);
    s0 += __shfl_xor_sync(0xffffffffu, s0, 2);
    s1 += __shfl_xor_sync(0xffffffffu, s1, 1);
    s1 += __shfl_xor_sync(0xffffffffu, s1, 2);
    if (tig == 0) {
        stats[(wn * 64 + arow) * 2]         = m0;
        stats[(wn * 64 + arow) * 2 + 1]     = s0;
        stats[(wn * 64 + arow + 8) * 2]     = m1;
        stats[(wn * 64 + arow + 8) * 2 + 1] = s1;
    }
    __syncthreads();
    float om0 = stats[((wn ^ 1) * 64 + arow) * 2];
    float os0 = stats[((wn ^ 1) * 64 + arow) * 2 + 1];
    float om1 = stats[((wn ^ 1) * 64 + arow + 8) * 2];
    float os1 = stats[((wn ^ 1) * 64 + arow + 8) * 2 + 1];
    float M0 = fmaxf(m0, om0), M1 = fmaxf(m1, om1);
    float S0 = s0 * __expf(m0 - M0) + os0 * __expf(om0 - M0);
    float S1 = s1 * __expf(m1 - M1) + os1 * __expf(om1 - M1);
    float sc0 = __expf(m0 - M0) / S0;
    float sc1 = __expf(m1 - M1) / S1;
    if (wn == 0 && tig == 0) {
        g_lse[((size_t)(b * HH + h)) * SS + tq0] = M0 + __logf(S0);
        g_lse[((size_t)(b * HH + h)) * SS + tq1] = M1 + __logf(S1);
    }

    // ---- convert p to half2 fragments (row gID -> pA, row gID+8 -> pB)
    __half2 pA[8], pB[8];
#pragma unroll
    for (int nt = 0; nt < 8; nt++) {
        pA[nt] = __floats2half2_rn(cqk[nt][0] * sc0, cqk[nt][1] * sc0);
        pB[nt] = __floats2half2_rn(cqk[nt][2] * sc1, cqk[nt][3] * sc1);
    }

    // ---- P @ V over this warp's 64-key half (K=64, 4 k16 steps), full f range (8 n-tiles)
    float oacc[8][4];
#pragma unroll
    for (int ft = 0; ft < 8; ft++)
#pragma unroll
        for (int r = 0; r < 4; r++) oacc[ft][r] = 0.f;

#pragma unroll
    for (int s = 0; s < 4; s++) {
        unsigned a0 = h2_u32(pA[2 * s]);
        unsigned a2 = h2_u32(pA[2 * s + 1]);
        unsigned a1 = h2_u32(pB[2 * s]);
        unsigned a3 = h2_u32(pB[2 * s + 1]);
        int jbase = wn * 64 + s * 16 + 2 * tig;
#pragma unroll
        for (int ft = 0; ft < 8; ft++) {
            unsigned b0 = *(unsigned*)&VT[(ft * 8 + gID) * 136 + jbase];
            unsigned b1 = *(unsigned*)&VT[(ft * 8 + gID) * 136 + jbase + 8];
            mma_f16(oacc[ft], a0, a1, a2, a3, b0, b1);
        }
    }

    // ---- sum wn partials via Dx, scatter to g_o
    if (wn == 1) {
#pragma unroll
        for (int ft = 0; ft < 8; ft++) {
            *(float2*)&Dx[arow * 66 + ft * 8 + 2 * tig]       = make_float2(oacc[ft][0], oacc[ft][1]);
            *(float2*)&Dx[(arow + 8) * 66 + ft * 8 + 2 * tig] = make_float2(oacc[ft][2], oacc[ft][3]);
        }
    }
    __syncthreads();
    if (wn == 0) {
        float* o0 = g_o + (((size_t)(b * HH + h)) * SS + tq0) * DD;
        float* o1 = g_o + (((size_t)(b * HH + h)) * SS + tq1) * DD;
#pragma unroll
        for (int ft = 0; ft < 8; ft++) {
            float2 d0 = *(float2*)&Dx[arow * 66 + ft * 8 + 2 * tig];
            float2 d1 = *(float2*)&Dx[(arow + 8) * 66 + ft * 8 + 2 * tig];
            *(float2*)&o0[ft * 8 + 2 * tig] = make_float2(oacc[ft][0] + d0.x, oacc[ft][1] + d0.y);
            *(float2*)&o1[ft * 8 + 2 * tig] = make_float2(oacc[ft][2] + d1.x, oacc[ft][3] + d1.y);
        }
    }
}

// ==================== Kernel 4: combine hash rounds ====================
__global__ __launch_bounds__(256) void combine_kernel(float* __restrict__ out) {
    const int gw = (blockIdx.x * 256 + threadIdx.x) >> 5;
    const int l  = threadIdx.x & 31;
    const int b  = gw >> 12, t = gw & (SS - 1);

    float lg[HH];
#pragma unroll
    for (int hh = 0; hh < HH; hh++) lg[hh] = g_lse[((size_t)(b * HH + hh)) * SS + t];
    float m = lg[0];
#pragma unroll
    for (int hh = 1; hh < HH; hh++) m = fmaxf(m, lg[hh]);
    float wv[HH];
    float wsum = 0.f;
#pragma unroll
    for (int hh = 0; hh < HH; hh++) { wv[hh] = __expf(lg[hh] - m); wsum += wv[hh]; }
    float inv = 1.0f / wsum;

    float2 accv = make_float2(0.f, 0.f);
#pragma unroll
    for (int hh = 0; hh < HH; hh++) {
        float2 ov = ((const float2*)(g_o + (((size_t)(b * HH + hh)) * SS + t) * DD))[l];
        float wgt = wv[hh] * inv;
        accv.x += wgt * ov.x;
        accv.y += wgt * ov.y;
    }
    ((float2*)(out + ((size_t)b * SS + t) * DD))[l] = accv;
}

// ==================== launch ====================
extern "C" void kernel_launch(void* const* d_in, const int* in_sizes, int n_in,
                              void* d_out, int out_size) {
    const float* qk  = (const float*)d_in[0];
    const float* v   = (const float*)d_in[1];
    const float* rot = (const float*)d_in[2];
    float* out = (float*)d_out;

    (void)in_sizes; (void)n_in; (void)out_size;

    const int hash_smem = 87040;   // 64*68*4 + 256*68*4
    const int attn_smem = 49920;   // tqi/tki/stats + Qsm + Ksm + VT
    cudaFuncSetAttribute(hash_kernel, cudaFuncAttributeMaxDynamicSharedMemorySize, hash_smem);
    cudaFuncSetAttribute(attn_kernel, cudaFuncAttributeMaxDynamicSharedMemorySize, attn_smem);

    hash_kernel<<<BB * (SS / 64), 256, hash_smem>>>(qk, rot);
    sort_kernel<<<BB * HH, 512>>>();
    attn_kernel<<<BB * CHK, 256, attn_smem>>>(qk, v);
    combine_kernel<<<(BB * SS) / 8, 256>>>(out);
}